// round 1
// baseline (speedup 1.0000x reference)
#include <cuda_runtime.h>
#include <cstdint>

// ---------------------------------------------------------------------------
// GCN_72971494359045: 2-layer GCN with sym-norm + self-loops + PReLU.
//   xi = [x | id]            (id is constant per node -> fold into c1)
//   h1 = prelu(GCNConv(xi, W1, b1), a1)
//   h2 = prelu(GCNConv(h1, W2, b2), a2)
// GCNConv: deg[v] = indeg(v)+1, dinv=rsqrt(deg),
//   out[d] = sum_{(s,d) in E} (x@W)[s]*dinv[s]*dinv[d] + (x@W)[d]*dinv[d]^2 + b
// ---------------------------------------------------------------------------

static constexpr int NNODES = 50000;
static constexpr int NEDGES = 800000;
static constexpr int INDIM  = 128;
static constexpr int ADDDIM = 8;
static constexpr int HID    = 256;
static constexpr int OUTD   = 128;

// -------------------- device scratch (static; no allocation) ---------------
__device__ float g_h[(size_t)NNODES * HID];     // GEMM output (h1, then reused for h2)
__device__ float g_acc[(size_t)NNODES * HID];   // scatter accumulator
__device__ float g_out1[(size_t)NNODES * HID];  // post-activation layer-1 output
__device__ float g_dinv[NNODES];
__device__ int   g_deg[NNODES];
__device__ float g_c1[HID];
__device__ int   g_is64;

// -------------------- edge-index dtype sniff -------------------------------
__global__ void k_detect(const long long* __restrict__ ei) {
    // If data is really int64 node indices, every value is in [0, NNODES).
    // If it's int32, the high words are random node ids -> huge int64 values.
    bool bad = false;
    for (int i = threadIdx.x; i < 512; i += 32) {
        long long v = ei[i];
        if (v < 0 || v >= NNODES) bad = true;
    }
    unsigned m = __ballot_sync(0xFFFFFFFFu, bad);
    if (threadIdx.x == 0) g_is64 = (m == 0u) ? 1 : 0;
}

// -------------------- zero helpers -----------------------------------------
__global__ void k_zero_f4(float4* p, int n4) {
    int i = blockIdx.x * blockDim.x + threadIdx.x;
    if (i < n4) p[i] = make_float4(0.f, 0.f, 0.f, 0.f);
}
__global__ void k_zero_i(int* p, int n) {
    int i = blockIdx.x * blockDim.x + threadIdx.x;
    if (i < n) p[i] = 0;
}

// -------------------- degree + dinv ----------------------------------------
__global__ void k_deg(const void* __restrict__ ei) {
    int i = blockIdx.x * blockDim.x + threadIdx.x;
    if (i >= NEDGES) return;
    int d;
    if (g_is64) d = (int)((const long long*)ei)[NEDGES + i];
    else        d = ((const int*)ei)[NEDGES + i];
    atomicAdd(&g_deg[d], 1);
}
__global__ void k_dinv() {
    int i = blockIdx.x * blockDim.x + threadIdx.x;
    if (i < NNODES) g_dinv[i] = rsqrtf((float)(g_deg[i] + 1));
}

// -------------------- c1 = id @ W1[128:136, :] ------------------------------
__global__ void k_c1(const float* __restrict__ idv, const float* __restrict__ W1) {
    int j = threadIdx.x;  // 256
    float s = 0.f;
#pragma unroll
    for (int t = 0; t < ADDDIM; t++) s += idv[t] * W1[(size_t)(INDIM + t) * HID + j];
    g_c1[j] = s;
}

// -------------------- tiled fp32 GEMM: C = A[M,K] @ B[K,N] (+ cvec) ---------
// BM=64, BN=64, BK=32, 256 threads, 4x4 micro-tiles.
template <int K, int N>
__global__ __launch_bounds__(256) void k_gemm(const float* __restrict__ A,
                                              const float* __restrict__ B,
                                              float* __restrict__ C,
                                              const float* __restrict__ cvec,
                                              int M) {
    constexpr int BM = 64, BN = 64, BK = 32;
    __shared__ float As[BM][BK + 1];
    __shared__ float Bs[BK][BN];

    const int tid = threadIdx.x;
    const int tx = tid & 15;       // output col group
    const int ty = tid >> 4;       // output row group
    const int row0 = blockIdx.y * BM;
    const int col0 = blockIdx.x * BN;

    float acc[4][4] = {};

    for (int k0 = 0; k0 < K; k0 += BK) {
        // load A tile (64 x 32), guard M
#pragma unroll
        for (int q = tid; q < BM * BK / 4; q += 256) {
            int r = q / (BK / 4);
            int c4 = q % (BK / 4);
            float4 v = make_float4(0.f, 0.f, 0.f, 0.f);
            int gr = row0 + r;
            if (gr < M) v = *(const float4*)&A[(size_t)gr * K + k0 + c4 * 4];
            As[r][c4 * 4 + 0] = v.x; As[r][c4 * 4 + 1] = v.y;
            As[r][c4 * 4 + 2] = v.z; As[r][c4 * 4 + 3] = v.w;
        }
        // load B tile (32 x 64) — K,N multiples of tile, no guard
#pragma unroll
        for (int q = tid; q < BK * BN / 4; q += 256) {
            int r = q / (BN / 4);
            int c4 = q % (BN / 4);
            *(float4*)&Bs[r][c4 * 4] = *(const float4*)&B[(size_t)(k0 + r) * N + col0 + c4 * 4];
        }
        __syncthreads();

#pragma unroll
        for (int k = 0; k < BK; k++) {
            float a[4];
#pragma unroll
            for (int i = 0; i < 4; i++) a[i] = As[ty * 4 + i][k];
            float4 bv = *(float4*)&Bs[k][tx * 4];
            float b[4] = {bv.x, bv.y, bv.z, bv.w};
#pragma unroll
            for (int i = 0; i < 4; i++)
#pragma unroll
                for (int j = 0; j < 4; j++) acc[i][j] += a[i] * b[j];
        }
        __syncthreads();
    }

    float4 cv = make_float4(0.f, 0.f, 0.f, 0.f);
    if (cvec) cv = *(const float4*)&cvec[col0 + tx * 4];
#pragma unroll
    for (int i = 0; i < 4; i++) {
        int r = row0 + ty * 4 + i;
        if (r < M) {
            float4 o = make_float4(acc[i][0] + cv.x, acc[i][1] + cv.y,
                                   acc[i][2] + cv.z, acc[i][3] + cv.w);
            *(float4*)&C[(size_t)r * N + col0 + tx * 4] = o;
        }
    }
}

// -------------------- edge scatter: acc[d] += h[s] * dinv[s]*dinv[d] --------
template <int F>
__global__ void k_scatter(const float* __restrict__ h, float* __restrict__ acc,
                          const void* __restrict__ ei) {
    const int lane = threadIdx.x & 31;
    const int warp = (blockIdx.x * blockDim.x + threadIdx.x) >> 5;
    const int nw = (gridDim.x * blockDim.x) >> 5;
    const long long* e64 = (const long long*)ei;
    const int* e32 = (const int*)ei;
    const int is64 = g_is64;

    for (int e = warp; e < NEDGES; e += nw) {
        int s, d;
        if (is64) { s = (int)e64[e]; d = (int)e64[NEDGES + e]; }
        else      { s = e32[e];      d = e32[NEDGES + e]; }
        float norm = g_dinv[s] * g_dinv[d];
        const float4* hp = (const float4*)(h + (size_t)s * F);
        float* ap = acc + (size_t)d * F;
#pragma unroll
        for (int it = 0; it < F / 128; it++) {
            int f4 = lane + it * 32;
            float4 v = hp[f4];
            atomicAdd(ap + f4 * 4 + 0, v.x * norm);
            atomicAdd(ap + f4 * 4 + 1, v.y * norm);
            atomicAdd(ap + f4 * 4 + 2, v.z * norm);
            atomicAdd(ap + f4 * 4 + 3, v.w * norm);
        }
    }
}

// -------------------- epilogue: out = prelu(acc + h*dinv^2 + b, a) ----------
template <int F>
__global__ void k_post(const float* __restrict__ acc, const float* __restrict__ h,
                       const float* __restrict__ bias, const float* __restrict__ av,
                       float* __restrict__ out) {
    int i4 = blockIdx.x * blockDim.x + threadIdx.x;      // float4 index
    if (i4 >= NNODES * F / 4) return;
    int v = (i4 * 4) / F;
    int col = (i4 * 4) % F;
    float dv = g_dinv[v];
    float w = dv * dv;
    float4 A = ((const float4*)acc)[i4];
    float4 H = ((const float4*)h)[i4];
    float4 B = *(const float4*)&bias[col];
    float4 S = *(const float4*)&av[col];
    float r0 = A.x + H.x * w + B.x;
    float r1 = A.y + H.y * w + B.y;
    float r2 = A.z + H.z * w + B.z;
    float r3 = A.w + H.w * w + B.w;
    float4 o;
    o.x = r0 >= 0.f ? r0 : S.x * r0;
    o.y = r1 >= 0.f ? r1 : S.y * r1;
    o.z = r2 >= 0.f ? r2 : S.z * r2;
    o.w = r3 >= 0.f ? r3 : S.w * r3;
    ((float4*)out)[i4] = o;
}

// -------------------- launch ------------------------------------------------
extern "C" void kernel_launch(void* const* d_in, const int* in_sizes, int n_in,
                              void* d_out, int out_size) {
    const float* x  = (const float*)d_in[0];
    const void*  ei = d_in[1];
    const float* idv = (const float*)d_in[2];
    const float* W1 = (const float*)d_in[3];
    const float* b1 = (const float*)d_in[4];
    const float* a1 = (const float*)d_in[5];
    const float* W2 = (const float*)d_in[6];
    const float* b2 = (const float*)d_in[7];
    const float* a2 = (const float*)d_in[8];
    float* out = (float*)d_out;

    float* d_h;    cudaGetSymbolAddress((void**)&d_h, g_h);
    float* d_acc;  cudaGetSymbolAddress((void**)&d_acc, g_acc);
    float* d_out1; cudaGetSymbolAddress((void**)&d_out1, g_out1);
    int*   d_deg;  cudaGetSymbolAddress((void**)&d_deg, g_deg);
    float* d_c1;   cudaGetSymbolAddress((void**)&d_c1, g_c1);

    const int T = 256;

    // 0) dtype sniff for edge_index
    k_detect<<<1, 32>>>((const long long*)ei);

    // 1) zero deg + acc (full HID width for layer 1)
    k_zero_i<<<(NNODES + T - 1) / T, T>>>(d_deg, NNODES);
    {
        int n4 = NNODES * HID / 4;
        k_zero_f4<<<(n4 + T - 1) / T, T>>>((float4*)d_acc, n4);
    }

    // 2) degree + dinv
    k_deg<<<(NEDGES + T - 1) / T, T>>>(ei);
    k_dinv<<<(NNODES + T - 1) / T, T>>>();

    // 3) c1 = id @ W1[128:136]
    k_c1<<<1, HID>>>(idv, W1);

    // 4) GEMM1: g_h = x @ W1[0:128] + c1
    {
        dim3 grid(HID / 64, (NNODES + 63) / 64);
        k_gemm<INDIM, HID><<<grid, 256>>>(x, W1, d_h, d_c1, NNODES);
    }

    // 5) scatter layer 1
    k_scatter<HID><<<148 * 16, 256>>>(d_h, d_acc, ei);

    // 6) epilogue layer 1 -> g_out1
    {
        int n4 = NNODES * HID / 4;
        k_post<HID><<<(n4 + T - 1) / T, T>>>(d_acc, d_h, b1, a1, d_out1);
    }

    // 7) zero acc for layer 2 (OUTD width)
    {
        int n4 = NNODES * OUTD / 4;
        k_zero_f4<<<(n4 + T - 1) / T, T>>>((float4*)d_acc, n4);
    }

    // 8) GEMM2: g_h = out1 @ W2
    {
        dim3 grid(OUTD / 64, (NNODES + 63) / 64);
        k_gemm<HID, OUTD><<<grid, 256>>>(d_out1, W2, d_h, nullptr, NNODES);
    }

    // 9) scatter layer 2
    k_scatter<OUTD><<<148 * 16, 256>>>(d_h, d_acc, ei);

    // 10) epilogue layer 2 -> d_out
    {
        int n4 = NNODES * OUTD / 4;
        k_post<OUTD><<<(n4 + T - 1) / T, T>>>(d_acc, d_h, b2, a2, out);
    }
}

// round 2
// speedup vs baseline: 2.6759x; 2.6759x over previous
#include <cuda_runtime.h>
#include <cstdint>

// ---------------------------------------------------------------------------
// GCN_72971494359045: 2-layer GCN, CSR-gather formulation (no scatter atomics)
//   h = (x|id) @ W1 + c1  -> per-dst gather with sym-norm + self-loop + b1 + prelu
//   -> @ W2 -> gather + b2 + prelu
// ---------------------------------------------------------------------------

static constexpr int NNODES = 50000;
static constexpr int NEDGES = 800000;
static constexpr int INDIM  = 128;
static constexpr int ADDDIM = 8;
static constexpr int HID    = 256;
static constexpr int OUTD   = 128;

// -------------------- device scratch ---------------------------------------
__device__ float g_h[(size_t)NNODES * HID];     // GEMM output
__device__ float g_out1[(size_t)NNODES * HID];  // layer-1 activation
__device__ float g_dinv[NNODES];
__device__ int   g_deg[NNODES];
__device__ int   g_off[NNODES + 1];
__device__ int   g_cur[NNODES];
__device__ int   g_src[NEDGES];                 // CSR-by-dst: source node ids
__device__ float g_c1[HID];
__device__ int   g_is64;

// -------------------- edge-index dtype sniff -------------------------------
__global__ void k_detect(const long long* __restrict__ ei) {
    bool bad = false;
    for (int i = threadIdx.x; i < 512; i += 32) {
        long long v = ei[i];
        if (v < 0 || v >= NNODES) bad = true;
    }
    unsigned m = __ballot_sync(0xFFFFFFFFu, bad);
    if (threadIdx.x == 0) g_is64 = (m == 0u) ? 1 : 0;
}

__global__ void k_zero_i(int* p, int n) {
    int i = blockIdx.x * blockDim.x + threadIdx.x;
    if (i < n) p[i] = 0;
}

// -------------------- degree histogram + dinv -------------------------------
__global__ void k_deg(const void* __restrict__ ei) {
    int i = blockIdx.x * blockDim.x + threadIdx.x;
    if (i >= NEDGES) return;
    int d;
    if (g_is64) d = (int)((const long long*)ei)[NEDGES + i];
    else        d = ((const int*)ei)[NEDGES + i];
    atomicAdd(&g_deg[d], 1);
}
__global__ void k_dinv() {
    int i = blockIdx.x * blockDim.x + threadIdx.x;
    if (i < NNODES) g_dinv[i] = rsqrtf((float)(g_deg[i] + 1));
}

// -------------------- exclusive scan of g_deg -> g_off, g_cur ---------------
__global__ void k_scan() {
    __shared__ int warpsum[32];
    __shared__ int chunk_total;
    const int t = threadIdx.x;               // 1024 threads
    const int lane = t & 31, wid = t >> 5;
    int run = 0;
    for (int base = 0; base < NNODES; base += 1024) {
        int i = base + t;
        int v = (i < NNODES) ? g_deg[i] : 0;
        int x = v;
#pragma unroll
        for (int o = 1; o < 32; o <<= 1) {
            int y = __shfl_up_sync(0xFFFFFFFFu, x, o);
            if (lane >= o) x += y;
        }
        if (lane == 31) warpsum[wid] = x;
        __syncthreads();
        if (wid == 0) {
            int w = warpsum[lane];
#pragma unroll
            for (int o = 1; o < 32; o <<= 1) {
                int y = __shfl_up_sync(0xFFFFFFFFu, w, o);
                if (lane >= o) w += y;
            }
            warpsum[lane] = w;
            if (lane == 31) chunk_total = w;
        }
        __syncthreads();
        int excl = run + (wid ? warpsum[wid - 1] : 0) + x - v;
        if (i < NNODES) { g_off[i] = excl; g_cur[i] = excl; }
        run += chunk_total;
        __syncthreads();
    }
    if (t == 0) g_off[NNODES] = run;
}

// -------------------- CSR fill (counting sort by dst) -----------------------
__global__ void k_csr(const void* __restrict__ ei) {
    int i = blockIdx.x * blockDim.x + threadIdx.x;
    if (i >= NEDGES) return;
    int s, d;
    if (g_is64) {
        s = (int)((const long long*)ei)[i];
        d = (int)((const long long*)ei)[NEDGES + i];
    } else {
        s = ((const int*)ei)[i];
        d = ((const int*)ei)[NEDGES + i];
    }
    int pos = atomicAdd(&g_cur[d], 1);
    g_src[pos] = s;
}

// -------------------- c1 = id @ W1[128:136, :] ------------------------------
__global__ void k_c1(const float* __restrict__ idv, const float* __restrict__ W1) {
    int j = threadIdx.x;  // 256
    float s = 0.f;
#pragma unroll
    for (int t = 0; t < ADDDIM; t++) s += idv[t] * W1[(size_t)(INDIM + t) * HID + j];
    g_c1[j] = s;
}

// -------------------- SGEMM: 128x128 tile, BK=8, 8x8 micro-tiles ------------
template <int K, int N>
__global__ __launch_bounds__(256) void k_gemm(const float* __restrict__ A,
                                              const float* __restrict__ B,
                                              float* __restrict__ C,
                                              const float* __restrict__ cvec,
                                              int M) {
    constexpr int BM = 128, BN = 128, BK = 8;
    __shared__ float As[BK][BM];   // transposed A tile
    __shared__ float Bs[BK][BN];

    const int tid = threadIdx.x;
    const int tx = tid & 15;        // 16 col groups of 8
    const int ty = tid >> 4;        // 16 row groups of 8
    const int row0 = blockIdx.y * BM;
    const int col0 = blockIdx.x * BN;

    // A-load mapping: thread loads float4 at row (tid/2), k-offset (tid%2)*4
    const int ar = tid >> 1;
    const int ak = (tid & 1) * 4;
    // B-load mapping: row tid/32, col4 (tid%32)
    const int br = tid >> 5;
    const int bc = (tid & 31) * 4;

    float acc[8][8] = {};

    for (int k0 = 0; k0 < K; k0 += BK) {
        float4 av = make_float4(0.f, 0.f, 0.f, 0.f);
        int gr = row0 + ar;
        if (gr < M) av = *(const float4*)&A[(size_t)gr * K + k0 + ak];
        As[ak + 0][ar] = av.x;
        As[ak + 1][ar] = av.y;
        As[ak + 2][ar] = av.z;
        As[ak + 3][ar] = av.w;
        *(float4*)&Bs[br][bc] = *(const float4*)&B[(size_t)(k0 + br) * N + col0 + bc];
        __syncthreads();

#pragma unroll
        for (int k = 0; k < BK; k++) {
            float4 a0 = *(float4*)&As[k][ty * 8];
            float4 a1 = *(float4*)&As[k][ty * 8 + 4];
            float4 b0 = *(float4*)&Bs[k][tx * 8];
            float4 b1 = *(float4*)&Bs[k][tx * 8 + 4];
            float a[8] = {a0.x, a0.y, a0.z, a0.w, a1.x, a1.y, a1.z, a1.w};
            float b[8] = {b0.x, b0.y, b0.z, b0.w, b1.x, b1.y, b1.z, b1.w};
#pragma unroll
            for (int i = 0; i < 8; i++)
#pragma unroll
                for (int j = 0; j < 8; j++) acc[i][j] += a[i] * b[j];
        }
        __syncthreads();
    }

    float cv[8] = {};
    if (cvec) {
        float4 c0 = *(const float4*)&cvec[col0 + tx * 8];
        float4 c1 = *(const float4*)&cvec[col0 + tx * 8 + 4];
        cv[0] = c0.x; cv[1] = c0.y; cv[2] = c0.z; cv[3] = c0.w;
        cv[4] = c1.x; cv[5] = c1.y; cv[6] = c1.z; cv[7] = c1.w;
    }
#pragma unroll
    for (int i = 0; i < 8; i++) {
        int r = row0 + ty * 8 + i;
        if (r < M) {
            float4 o0 = make_float4(acc[i][0] + cv[0], acc[i][1] + cv[1],
                                    acc[i][2] + cv[2], acc[i][3] + cv[3]);
            float4 o1 = make_float4(acc[i][4] + cv[4], acc[i][5] + cv[5],
                                    acc[i][6] + cv[6], acc[i][7] + cv[7]);
            *(float4*)&C[(size_t)r * N + col0 + tx * 8] = o0;
            *(float4*)&C[(size_t)r * N + col0 + tx * 8 + 4] = o1;
        }
    }
}

// -------------------- gather: warp per node, fused epilogue -----------------
// out[v] = prelu( sum_{s in nbr(v)} h[s]*dinv[s]*dinv[v] + h[v]*dinv[v]^2 + b, a )
template <int F>
__global__ __launch_bounds__(256) void k_gather(const float* __restrict__ h,
                                                const float* __restrict__ bias,
                                                const float* __restrict__ slope,
                                                float* __restrict__ out) {
    const int lane = threadIdx.x & 31;
    const int node = (blockIdx.x * blockDim.x + threadIdx.x) >> 5;
    if (node >= NNODES) return;

    const float dv = g_dinv[node];
    const int e0 = g_off[node];
    const int e1 = g_off[node + 1];

    float4 acc0 = make_float4(0.f, 0.f, 0.f, 0.f);
    float4 acc1 = make_float4(0.f, 0.f, 0.f, 0.f);

    for (int e = e0; e < e1; e++) {
        int s = __ldg(&g_src[e]);
        float w = __ldg(&g_dinv[s]) * dv;
        const float4* hp = (const float4*)(h + (size_t)s * F);
        float4 v0 = __ldg(&hp[lane]);
        acc0.x += v0.x * w; acc0.y += v0.y * w;
        acc0.z += v0.z * w; acc0.w += v0.w * w;
        if (F == 256) {
            float4 v1 = __ldg(&hp[32 + lane]);
            acc1.x += v1.x * w; acc1.y += v1.y * w;
            acc1.z += v1.z * w; acc1.w += v1.w * w;
        }
    }

    // self-loop
    {
        float w = dv * dv;
        const float4* hp = (const float4*)(h + (size_t)node * F);
        float4 v0 = hp[lane];
        acc0.x += v0.x * w; acc0.y += v0.y * w;
        acc0.z += v0.z * w; acc0.w += v0.w * w;
        if (F == 256) {
            float4 v1 = hp[32 + lane];
            acc1.x += v1.x * w; acc1.y += v1.y * w;
            acc1.z += v1.z * w; acc1.w += v1.w * w;
        }
    }

    float* op = out + (size_t)node * F;
    {
        float4 B = *(const float4*)&bias[lane * 4];
        float4 S = *(const float4*)&slope[lane * 4];
        float r0 = acc0.x + B.x, r1 = acc0.y + B.y;
        float r2 = acc0.z + B.z, r3 = acc0.w + B.w;
        float4 o;
        o.x = r0 >= 0.f ? r0 : S.x * r0;
        o.y = r1 >= 0.f ? r1 : S.y * r1;
        o.z = r2 >= 0.f ? r2 : S.z * r2;
        o.w = r3 >= 0.f ? r3 : S.w * r3;
        *(float4*)&op[lane * 4] = o;
    }
    if (F == 256) {
        float4 B = *(const float4*)&bias[128 + lane * 4];
        float4 S = *(const float4*)&slope[128 + lane * 4];
        float r0 = acc1.x + B.x, r1 = acc1.y + B.y;
        float r2 = acc1.z + B.z, r3 = acc1.w + B.w;
        float4 o;
        o.x = r0 >= 0.f ? r0 : S.x * r0;
        o.y = r1 >= 0.f ? r1 : S.y * r1;
        o.z = r2 >= 0.f ? r2 : S.z * r2;
        o.w = r3 >= 0.f ? r3 : S.w * r3;
        *(float4*)&op[128 + lane * 4] = o;
    }
}

// -------------------- launch ------------------------------------------------
extern "C" void kernel_launch(void* const* d_in, const int* in_sizes, int n_in,
                              void* d_out, int out_size) {
    const float* x  = (const float*)d_in[0];
    const void*  ei = d_in[1];
    const float* idv = (const float*)d_in[2];
    const float* W1 = (const float*)d_in[3];
    const float* b1 = (const float*)d_in[4];
    const float* a1 = (const float*)d_in[5];
    const float* W2 = (const float*)d_in[6];
    const float* b2 = (const float*)d_in[7];
    const float* a2 = (const float*)d_in[8];
    float* out = (float*)d_out;

    float* d_h;    cudaGetSymbolAddress((void**)&d_h, g_h);
    float* d_out1; cudaGetSymbolAddress((void**)&d_out1, g_out1);
    int*   d_deg;  cudaGetSymbolAddress((void**)&d_deg, g_deg);
    float* d_c1;   cudaGetSymbolAddress((void**)&d_c1, g_c1);

    const int T = 256;

    k_detect<<<1, 32>>>((const long long*)ei);
    k_zero_i<<<(NNODES + T - 1) / T, T>>>(d_deg, NNODES);
    k_deg<<<(NEDGES + T - 1) / T, T>>>(ei);
    k_dinv<<<(NNODES + T - 1) / T, T>>>();
    k_scan<<<1, 1024>>>();
    k_csr<<<(NEDGES + T - 1) / T, T>>>(ei);
    k_c1<<<1, HID>>>(idv, W1);

    // GEMM1: g_h = x @ W1[0:128] + c1
    {
        dim3 grid(HID / 128, (NNODES + 127) / 128);
        k_gemm<INDIM, HID><<<grid, 256>>>(x, W1, d_h, d_c1, NNODES);
    }
    // gather layer 1 (fused bias + prelu) -> g_out1
    k_gather<HID><<<(NNODES * 32 + T - 1) / T, T>>>(d_h, b1, a1, d_out1);

    // GEMM2: g_h = out1 @ W2
    {
        dim3 grid(OUTD / 128, (NNODES + 127) / 128);
        k_gemm<HID, OUTD><<<grid, 256>>>(d_out1, W2, d_h, nullptr, NNODES);
    }
    // gather layer 2 -> out
    k_gather<OUTD><<<(NNODES * 32 + T - 1) / T, T>>>(d_h, b2, a2, out);
}

// round 4
// speedup vs baseline: 3.3427x; 1.2492x over previous
#include <cuda_runtime.h>
#include <cuda_bf16.h>
#include <cstdint>

// ---------------------------------------------------------------------------
// 2-layer GCN. Pipeline:
//   CSR build -> gather1(x,128d, + q) -> mma.sync bf16 GEMM1 (split-bf16,
//   fused q*c1+b1+prelu epilogue, emits bf16 hi/lo) -> GEMM2 -> gather2(+b2+prelu)
// ---------------------------------------------------------------------------

static constexpr int NNODES = 50000;
static constexpr int NEDGES = 800000;
static constexpr int INDIM  = 128;
static constexpr int ADDDIM = 8;
static constexpr int HID    = 256;
static constexpr int OUTD   = 128;

// -------------------- device scratch (16B aligned for uint4 access) ---------
__device__ __align__(16) __nv_bfloat16 g_aggx_hi[(size_t)NNODES * INDIM];
__device__ __align__(16) __nv_bfloat16 g_aggx_lo[(size_t)NNODES * INDIM];
__device__ __align__(16) __nv_bfloat16 g_h1_hi[(size_t)NNODES * HID];
__device__ __align__(16) __nv_bfloat16 g_h1_lo[(size_t)NNODES * HID];
__device__ __align__(16) float g_h2[(size_t)NNODES * OUTD];
__device__ float g_q[NNODES];
__device__ float g_dinv[NNODES];
__device__ int   g_deg[NNODES];
__device__ int   g_off[NNODES + 1];
__device__ int   g_cur[NNODES];
__device__ int   g_src[NEDGES];
__device__ float g_c1[HID];
__device__ __align__(16) __nv_bfloat16 g_wt1_hi[HID * INDIM], g_wt1_lo[HID * INDIM]; // [256][128]
__device__ __align__(16) __nv_bfloat16 g_wt2_hi[OUTD * HID],  g_wt2_lo[OUTD * HID];  // [128][256]
__device__ int g_is64;

// -------------------- warp-mma helpers --------------------------------------
__device__ __forceinline__ uint32_t smem_u32(const void* p) {
    return (uint32_t)__cvta_generic_to_shared(p);
}
__device__ __forceinline__ void ldsm_x4(uint32_t r[4], uint32_t addr) {
    asm volatile("ldmatrix.sync.aligned.m8n8.x4.shared.b16 {%0,%1,%2,%3}, [%4];"
                 : "=r"(r[0]), "=r"(r[1]), "=r"(r[2]), "=r"(r[3]) : "r"(addr));
}
__device__ __forceinline__ void mma_bf16(float* c, const uint32_t* a,
                                         uint32_t b0, uint32_t b1) {
    asm volatile(
        "mma.sync.aligned.m16n8k16.row.col.f32.bf16.bf16.f32 "
        "{%0,%1,%2,%3}, {%4,%5,%6,%7}, {%8,%9}, {%0,%1,%2,%3};"
        : "+f"(c[0]), "+f"(c[1]), "+f"(c[2]), "+f"(c[3])
        : "r"(a[0]), "r"(a[1]), "r"(a[2]), "r"(a[3]), "r"(b0), "r"(b1));
}

// -------------------- small prep kernels ------------------------------------
__global__ void k_detect(const long long* __restrict__ ei) {
    bool bad = false;
    for (int i = threadIdx.x; i < 512; i += 32) {
        long long v = ei[i];
        if (v < 0 || v >= NNODES) bad = true;
    }
    unsigned m = __ballot_sync(0xFFFFFFFFu, bad);
    if (threadIdx.x == 0) g_is64 = (m == 0u) ? 1 : 0;
}
__global__ void k_zero_deg() {
    int i = blockIdx.x * blockDim.x + threadIdx.x;
    if (i < NNODES) g_deg[i] = 0;
}
__global__ void k_deg(const void* __restrict__ ei) {
    int i = blockIdx.x * blockDim.x + threadIdx.x;
    if (i >= NEDGES) return;
    int d;
    if (g_is64) d = (int)((const long long*)ei)[NEDGES + i];
    else        d = ((const int*)ei)[NEDGES + i];
    atomicAdd(&g_deg[d], 1);
}
__global__ void k_dinv() {
    int i = blockIdx.x * blockDim.x + threadIdx.x;
    if (i < NNODES) g_dinv[i] = rsqrtf((float)(g_deg[i] + 1));
}
__global__ void k_scan() {
    __shared__ int warpsum[32];
    __shared__ int chunk_total;
    const int t = threadIdx.x;               // 1024
    const int lane = t & 31, wid = t >> 5;
    int run = 0;
    for (int base = 0; base < NNODES; base += 1024) {
        int i = base + t;
        int v = (i < NNODES) ? g_deg[i] : 0;
        int x = v;
#pragma unroll
        for (int o = 1; o < 32; o <<= 1) {
            int y = __shfl_up_sync(0xFFFFFFFFu, x, o);
            if (lane >= o) x += y;
        }
        if (lane == 31) warpsum[wid] = x;
        __syncthreads();
        if (wid == 0) {
            int w = warpsum[lane];
#pragma unroll
            for (int o = 1; o < 32; o <<= 1) {
                int y = __shfl_up_sync(0xFFFFFFFFu, w, o);
                if (lane >= o) w += y;
            }
            warpsum[lane] = w;
            if (lane == 31) chunk_total = w;
        }
        __syncthreads();
        int excl = run + (wid ? warpsum[wid - 1] : 0) + x - v;
        if (i < NNODES) { g_off[i] = excl; g_cur[i] = excl; }
        run += chunk_total;
        __syncthreads();
    }
    if (t == 0) g_off[NNODES] = run;
}
__global__ void k_csr(const void* __restrict__ ei) {
    int i = blockIdx.x * blockDim.x + threadIdx.x;
    if (i >= NEDGES) return;
    int s, d;
    if (g_is64) {
        s = (int)((const long long*)ei)[i];
        d = (int)((const long long*)ei)[NEDGES + i];
    } else {
        s = ((const int*)ei)[i];
        d = ((const int*)ei)[NEDGES + i];
    }
    int pos = atomicAdd(&g_cur[d], 1);
    g_src[pos] = s;
}
__global__ void k_c1(const float* __restrict__ idv, const float* __restrict__ W1) {
    int j = threadIdx.x;  // 256
    float s = 0.f;
#pragma unroll
    for (int t = 0; t < ADDDIM; t++) s += idv[t] * W1[(size_t)(INDIM + t) * HID + j];
    g_c1[j] = s;
}
// transpose + bf16 split: Wt[o][i] = W[i][o]
__global__ void k_wprep(const float* __restrict__ W, __nv_bfloat16* __restrict__ hi,
                        __nv_bfloat16* __restrict__ lo, int IN, int OUT) {
    int idx = blockIdx.x * blockDim.x + threadIdx.x;
    if (idx >= IN * OUT) return;
    int o = idx / IN, i = idx % IN;
    float v = W[(size_t)i * OUT + o];
    __nv_bfloat16 h = __float2bfloat16_rn(v);
    float r = v - __bfloat162float(h);
    hi[idx] = h;
    lo[idx] = __float2bfloat16_rn(r);
}

// -------------------- gather1: agg(x) -> bf16 hi/lo + q ---------------------
__global__ __launch_bounds__(256) void k_gather1(const float* __restrict__ x) {
    const int lane = threadIdx.x & 31;
    const int node = (blockIdx.x * blockDim.x + threadIdx.x) >> 5;
    if (node >= NNODES) return;
    const float dv = g_dinv[node];
    const int e0 = g_off[node], e1 = g_off[node + 1];
    float4 acc = make_float4(0.f, 0.f, 0.f, 0.f);
    float q = 0.f;
    for (int e = e0; e < e1; e++) {
        int s = __ldg(&g_src[e]);
        float w = __ldg(&g_dinv[s]) * dv;
        q += w;
        float4 v = __ldg((const float4*)(x + (size_t)s * INDIM) + lane);
        acc.x += v.x * w; acc.y += v.y * w; acc.z += v.z * w; acc.w += v.w * w;
    }
    {
        float w = dv * dv;
        q += w;
        float4 v = __ldg((const float4*)(x + (size_t)node * INDIM) + lane);
        acc.x += v.x * w; acc.y += v.y * w; acc.z += v.z * w; acc.w += v.w * w;
    }
    float vals[4] = {acc.x, acc.y, acc.z, acc.w};
    uint32_t hp[2], lp[2];
#pragma unroll
    for (int p = 0; p < 2; p++) {
        __nv_bfloat16 h0 = __float2bfloat16_rn(vals[p * 2]);
        __nv_bfloat16 h1 = __float2bfloat16_rn(vals[p * 2 + 1]);
        __nv_bfloat16 l0 = __float2bfloat16_rn(vals[p * 2] - __bfloat162float(h0));
        __nv_bfloat16 l1 = __float2bfloat16_rn(vals[p * 2 + 1] - __bfloat162float(h1));
        hp[p] = (uint32_t)__bfloat16_as_ushort(h0) | ((uint32_t)__bfloat16_as_ushort(h1) << 16);
        lp[p] = (uint32_t)__bfloat16_as_ushort(l0) | ((uint32_t)__bfloat16_as_ushort(l1) << 16);
    }
    size_t base = (size_t)node * INDIM + lane * 4;
    *(uint2*)&g_aggx_hi[base] = make_uint2(hp[0], hp[1]);
    *(uint2*)&g_aggx_lo[base] = make_uint2(lp[0], lp[1]);
    if (lane == 0) g_q[node] = q;
}

// -------------------- mma.sync split-bf16 GEMM ------------------------------
// C[M,NTOT] = (Ahi+Alo)[M,K] @ (Bhi+Blo)[NTOT,K]^T, 3-term compensation.
// CTA tile 128x128, 8 warps in 4x2, warp tile 32x64, BK=16.
// L1: epilogue prelu(D + q*c1 + bias) -> bf16 hi/lo. else: raw fp32.
template <int K, int NTOT, bool L1>
__global__ __launch_bounds__(256) void k_mma(
    const __nv_bfloat16* __restrict__ Ahi, const __nv_bfloat16* __restrict__ Alo,
    const __nv_bfloat16* __restrict__ Bhi, const __nv_bfloat16* __restrict__ Blo,
    const float* __restrict__ bias, const float* __restrict__ slope,
    __nv_bfloat16* __restrict__ OutHi, __nv_bfloat16* __restrict__ OutLo,
    float* __restrict__ OutF, int M) {
    constexpr int BK = 16, SA = 24;       // padded stride (48B): conflict-free ldmatrix
    constexpr int NSEG = K / BK;
    constexpr int NCH = 3 * NSEG;

    __shared__ __align__(16) __nv_bfloat16 As[128 * SA];
    __shared__ __align__(16) __nv_bfloat16 Bs[128 * SA];

    const int t = threadIdx.x;
    const int lane = t & 31, warp = t >> 5;
    const int wm0 = (warp >> 1) * 32;      // warp row offset in tile
    const int wn0 = (warp & 1) * 64;       // warp col offset in tile
    const int row0 = blockIdx.y * 128;
    const int n0 = blockIdx.x * 128;

    // global<->smem staging: thread loads 8 bf16 of row lr, col-half lk
    const int lr = t >> 1, lk = (t & 1) * 8;

    // ldmatrix source addresses (constant across chunks)
    uint32_t a_addr[2], b_addr[4];
#pragma unroll
    for (int mi = 0; mi < 2; mi++)
        a_addr[mi] = smem_u32(As) +
            ((wm0 + mi * 16 + (lane & 15)) * SA + (lane >> 4) * 8) * 2;
#pragma unroll
    for (int nq = 0; nq < 4; nq++)
        b_addr[nq] = smem_u32(Bs) +
            ((wn0 + nq * 16 + (lane & 7) + ((lane >> 4) & 1) * 8) * SA +
             ((lane >> 3) & 1) * 8) * 2;

    float acc[2][8][4] = {};

    for (int c = 0; c < NCH; c++) {
        const int seg = c % NSEG;
        const int phase = c / NSEG;
        const __nv_bfloat16* Ap = (phase == 1) ? Alo : Ahi;
        const __nv_bfloat16* Bp = (phase == 2) ? Blo : Bhi;
        const int k0 = seg * BK;

        uint4 va = make_uint4(0, 0, 0, 0);
        int gr = row0 + lr;
        if (gr < M) va = *(const uint4*)(Ap + (size_t)gr * K + k0 + lk);
        *(uint4*)(As + lr * SA + lk) = va;
        uint4 vb = *(const uint4*)(Bp + (size_t)(n0 + lr) * K + k0 + lk);
        *(uint4*)(Bs + lr * SA + lk) = vb;
        __syncthreads();

        uint32_t af[2][4], bf[4][4];
#pragma unroll
        for (int mi = 0; mi < 2; mi++) ldsm_x4(af[mi], a_addr[mi]);
#pragma unroll
        for (int nq = 0; nq < 4; nq++) ldsm_x4(bf[nq], b_addr[nq]);
#pragma unroll
        for (int mi = 0; mi < 2; mi++)
#pragma unroll
            for (int nq = 0; nq < 4; nq++) {
                mma_bf16(acc[mi][nq * 2],     af[mi], bf[nq][0], bf[nq][1]);
                mma_bf16(acc[mi][nq * 2 + 1], af[mi], bf[nq][2], bf[nq][3]);
            }
        __syncthreads();
    }

    // -------------------- epilogue ------------------------------------------
    // frag (mi,nt): rows r0 = row0+wm0+mi*16+lane/4, r1 = r0+8
    //              cols c0 = n0+wn0+nt*8+(lane%4)*2, c0+1
    float qv[2][2];
    if (L1) {
#pragma unroll
        for (int mi = 0; mi < 2; mi++) {
            int r0 = row0 + wm0 + mi * 16 + (lane >> 2);
            qv[mi][0] = (r0 < M) ? __ldg(&g_q[r0]) : 0.f;
            qv[mi][1] = (r0 + 8 < M) ? __ldg(&g_q[r0 + 8]) : 0.f;
        }
    }
#pragma unroll
    for (int mi = 0; mi < 2; mi++) {
        int r0 = row0 + wm0 + mi * 16 + (lane >> 2);
#pragma unroll
        for (int nt = 0; nt < 8; nt++) {
            int c0 = n0 + wn0 + nt * 8 + (lane & 3) * 2;
            if (L1) {
                float cc0 = __ldg(&g_c1[c0]),   cc1 = __ldg(&g_c1[c0 + 1]);
                float bb0 = __ldg(&bias[c0]),   bb1 = __ldg(&bias[c0 + 1]);
                float ss0 = __ldg(&slope[c0]),  ss1 = __ldg(&slope[c0 + 1]);
#pragma unroll
                for (int h = 0; h < 2; h++) {   // h=0: r0, h=1: r0+8
                    int r = r0 + h * 8;
                    if (r >= M) continue;
                    float v0 = acc[mi][nt][h * 2]     + qv[mi][h] * cc0 + bb0;
                    float v1 = acc[mi][nt][h * 2 + 1] + qv[mi][h] * cc1 + bb1;
                    v0 = v0 >= 0.f ? v0 : ss0 * v0;
                    v1 = v1 >= 0.f ? v1 : ss1 * v1;
                    __nv_bfloat16 h0 = __float2bfloat16_rn(v0);
                    __nv_bfloat16 h1 = __float2bfloat16_rn(v1);
                    __nv_bfloat16 l0 = __float2bfloat16_rn(v0 - __bfloat162float(h0));
                    __nv_bfloat16 l1 = __float2bfloat16_rn(v1 - __bfloat162float(h1));
                    size_t o = (size_t)r * NTOT + c0;
                    *(uint32_t*)(OutHi + o) = (uint32_t)__bfloat16_as_ushort(h0) |
                                              ((uint32_t)__bfloat16_as_ushort(h1) << 16);
                    *(uint32_t*)(OutLo + o) = (uint32_t)__bfloat16_as_ushort(l0) |
                                              ((uint32_t)__bfloat16_as_ushort(l1) << 16);
                }
            } else {
#pragma unroll
                for (int h = 0; h < 2; h++) {
                    int r = r0 + h * 8;
                    if (r >= M) continue;
                    *(float2*)(OutF + (size_t)r * NTOT + c0) =
                        make_float2(acc[mi][nt][h * 2], acc[mi][nt][h * 2 + 1]);
                }
            }
        }
    }
}

// -------------------- gather2: 128-dim, fused bias+prelu --------------------
__global__ __launch_bounds__(256) void k_gather2(const float* __restrict__ bias,
                                                 const float* __restrict__ slope,
                                                 float* __restrict__ out) {
    const int lane = threadIdx.x & 31;
    const int node = (blockIdx.x * blockDim.x + threadIdx.x) >> 5;
    if (node >= NNODES) return;
    const float dv = g_dinv[node];
    const int e0 = g_off[node], e1 = g_off[node + 1];
    float4 acc = make_float4(0.f, 0.f, 0.f, 0.f);
    const float* h = g_h2;
    for (int e = e0; e < e1; e++) {
        int s = __ldg(&g_src[e]);
        float w = __ldg(&g_dinv[s]) * dv;
        float4 v = __ldg((const float4*)(h + (size_t)s * OUTD) + lane);
        acc.x += v.x * w; acc.y += v.y * w; acc.z += v.z * w; acc.w += v.w * w;
    }
    {
        float w = dv * dv;
        float4 v = __ldg((const float4*)(h + (size_t)node * OUTD) + lane);
        acc.x += v.x * w; acc.y += v.y * w; acc.z += v.z * w; acc.w += v.w * w;
    }
    float4 B = *(const float4*)&bias[lane * 4];
    float4 S = *(const float4*)&slope[lane * 4];
    float r0 = acc.x + B.x, r1 = acc.y + B.y, r2 = acc.z + B.z, r3 = acc.w + B.w;
    float4 o;
    o.x = r0 >= 0.f ? r0 : S.x * r0;
    o.y = r1 >= 0.f ? r1 : S.y * r1;
    o.z = r2 >= 0.f ? r2 : S.z * r2;
    o.w = r3 >= 0.f ? r3 : S.w * r3;
    *(float4*)&out[(size_t)node * OUTD + lane * 4] = o;
}

// -------------------- launch ------------------------------------------------
extern "C" void kernel_launch(void* const* d_in, const int* in_sizes, int n_in,
                              void* d_out, int out_size) {
    const float* x  = (const float*)d_in[0];
    const void*  ei = d_in[1];
    const float* idv = (const float*)d_in[2];
    const float* W1 = (const float*)d_in[3];
    const float* b1 = (const float*)d_in[4];
    const float* a1 = (const float*)d_in[5];
    const float* W2 = (const float*)d_in[6];
    const float* b2 = (const float*)d_in[7];
    const float* a2 = (const float*)d_in[8];
    float* out = (float*)d_out;

    __nv_bfloat16 *d_axh, *d_axl, *d_h1h, *d_h1l, *d_w1h, *d_w1l, *d_w2h, *d_w2l;
    float *d_h2;
    cudaGetSymbolAddress((void**)&d_axh, g_aggx_hi);
    cudaGetSymbolAddress((void**)&d_axl, g_aggx_lo);
    cudaGetSymbolAddress((void**)&d_h1h, g_h1_hi);
    cudaGetSymbolAddress((void**)&d_h1l, g_h1_lo);
    cudaGetSymbolAddress((void**)&d_w1h, g_wt1_hi);
    cudaGetSymbolAddress((void**)&d_w1l, g_wt1_lo);
    cudaGetSymbolAddress((void**)&d_w2h, g_wt2_hi);
    cudaGetSymbolAddress((void**)&d_w2l, g_wt2_lo);
    cudaGetSymbolAddress((void**)&d_h2, g_h2);

    const int T = 256;

    k_detect<<<1, 32>>>((const long long*)ei);
    k_zero_deg<<<(NNODES + T - 1) / T, T>>>();
    k_deg<<<(NEDGES + T - 1) / T, T>>>(ei);
    k_dinv<<<(NNODES + T - 1) / T, T>>>();
    k_scan<<<1, 1024>>>();
    k_csr<<<(NEDGES + T - 1) / T, T>>>(ei);
    k_c1<<<1, HID>>>(idv, W1);
    k_wprep<<<(INDIM * HID + T - 1) / T, T>>>(W1, d_w1h, d_w1l, INDIM, HID);
    k_wprep<<<(HID * OUTD + T - 1) / T, T>>>(W2, d_w2h, d_w2l, HID, OUTD);

    k_gather1<<<(NNODES * 32 + T - 1) / T, T>>>(x);

    {   // GEMM1: [50000,128] x [256,128]^T -> h1 bf16 hi/lo (fused epilogue)
        dim3 grid(HID / 128, (NNODES + 127) / 128);
        k_mma<INDIM, HID, true><<<grid, 256>>>(d_axh, d_axl, d_w1h, d_w1l,
                                               b1, a1, d_h1h, d_h1l, nullptr, NNODES);
    }
    {   // GEMM2: [50000,256] x [128,256]^T -> h2 fp32
        dim3 grid(OUTD / 128, (NNODES + 127) / 128);
        k_mma<HID, OUTD, false><<<grid, 256>>>(d_h1h, d_h1l, d_w2h, d_w2l,
                                               nullptr, nullptr, nullptr, nullptr,
                                               d_h2, NNODES);
    }
    k_gather2<<<(NNODES * 32 + T - 1) / T, T>>>(b2, a2, out);
}

// round 5
// speedup vs baseline: 4.0770x; 1.2197x over previous
#include <cuda_runtime.h>
#include <cuda_bf16.h>
#include <cstdint>

// ---------------------------------------------------------------------------
// 2-layer GCN. CSR gather + split-bf16 mma.sync GEMMs (double-buffered cp.async)
// ---------------------------------------------------------------------------

static constexpr int NNODES = 50000;
static constexpr int NEDGES = 800000;
static constexpr int INDIM  = 128;
static constexpr int ADDDIM = 8;
static constexpr int HID    = 256;
static constexpr int OUTD   = 128;

// -------------------- device scratch ----------------------------------------
__device__ __align__(16) __nv_bfloat16 g_aggx_hi[(size_t)NNODES * INDIM];
__device__ __align__(16) __nv_bfloat16 g_aggx_lo[(size_t)NNODES * INDIM];
__device__ __align__(16) __nv_bfloat16 g_h1_hi[(size_t)NNODES * HID];
__device__ __align__(16) __nv_bfloat16 g_h1_lo[(size_t)NNODES * HID];
__device__ __align__(16) float g_h2[(size_t)NNODES * OUTD];
__device__ float g_q[NNODES];
__device__ float g_dinv[NNODES];
__device__ int   g_deg[NNODES];
__device__ int   g_off[NNODES + 1];
__device__ int   g_cur[NNODES];
__device__ int   g_src[NEDGES];
__device__ float g_c1[HID];
__device__ __align__(16) __nv_bfloat16 g_wt1_hi[HID * INDIM], g_wt1_lo[HID * INDIM];
__device__ __align__(16) __nv_bfloat16 g_wt2_hi[OUTD * HID],  g_wt2_lo[OUTD * HID];
__device__ int g_is64;

// -------------------- asm helpers -------------------------------------------
__device__ __forceinline__ uint32_t smem_u32(const void* p) {
    return (uint32_t)__cvta_generic_to_shared(p);
}
__device__ __forceinline__ void ldsm_x4(uint32_t r[4], uint32_t addr) {
    asm volatile("ldmatrix.sync.aligned.m8n8.x4.shared.b16 {%0,%1,%2,%3}, [%4];"
                 : "=r"(r[0]), "=r"(r[1]), "=r"(r[2]), "=r"(r[3]) : "r"(addr));
}
__device__ __forceinline__ void mma_bf16(float* c, const uint32_t* a,
                                         uint32_t b0, uint32_t b1) {
    asm volatile(
        "mma.sync.aligned.m16n8k16.row.col.f32.bf16.bf16.f32 "
        "{%0,%1,%2,%3}, {%4,%5,%6,%7}, {%8,%9}, {%0,%1,%2,%3};"
        : "+f"(c[0]), "+f"(c[1]), "+f"(c[2]), "+f"(c[3])
        : "r"(a[0]), "r"(a[1]), "r"(a[2]), "r"(a[3]), "r"(b0), "r"(b1));
}
__device__ __forceinline__ void cp16(uint32_t dst, const void* src, uint32_t sz) {
    asm volatile("cp.async.cg.shared.global [%0], [%1], 16, %2;"
                 :: "r"(dst), "l"(src), "r"(sz) : "memory");
}
__device__ __forceinline__ void cp_commit() {
    asm volatile("cp.async.commit_group;" ::: "memory");
}
template <int N>
__device__ __forceinline__ void cp_wait() {
    asm volatile("cp.async.wait_group %0;" :: "n"(N) : "memory");
}

// -------------------- prep kernels ------------------------------------------
__global__ void k_detect_zero(const long long* __restrict__ ei) {
    int i = blockIdx.x * blockDim.x + threadIdx.x;
    if (i < NNODES) g_deg[i] = 0;
    if (blockIdx.x == 0 && threadIdx.x < 32) {
        bool bad = false;
        for (int j = threadIdx.x; j < 512; j += 32) {
            long long v = ei[j];
            if (v < 0 || v >= NNODES) bad = true;
        }
        unsigned m = __ballot_sync(0xFFFFFFFFu, bad);
        if (threadIdx.x == 0) g_is64 = (m == 0u) ? 1 : 0;
    }
}
__global__ void k_deg(const void* __restrict__ ei) {
    int i = blockIdx.x * blockDim.x + threadIdx.x;
    if (i >= NEDGES) return;
    int d;
    if (g_is64) d = (int)((const long long*)ei)[NEDGES + i];
    else        d = ((const int*)ei)[NEDGES + i];
    atomicAdd(&g_deg[d], 1);
}
__global__ void k_scan() {   // also writes dinv
    __shared__ int warpsum[32];
    __shared__ int chunk_total;
    const int t = threadIdx.x;               // 1024
    const int lane = t & 31, wid = t >> 5;
    int run = 0;
    for (int base = 0; base < NNODES; base += 1024) {
        int i = base + t;
        int v = (i < NNODES) ? g_deg[i] : 0;
        if (i < NNODES) g_dinv[i] = rsqrtf((float)(v + 1));
        int x = v;
#pragma unroll
        for (int o = 1; o < 32; o <<= 1) {
            int y = __shfl_up_sync(0xFFFFFFFFu, x, o);
            if (lane >= o) x += y;
        }
        if (lane == 31) warpsum[wid] = x;
        __syncthreads();
        if (wid == 0) {
            int w = warpsum[lane];
#pragma unroll
            for (int o = 1; o < 32; o <<= 1) {
                int y = __shfl_up_sync(0xFFFFFFFFu, w, o);
                if (lane >= o) w += y;
            }
            warpsum[lane] = w;
            if (lane == 31) chunk_total = w;
        }
        __syncthreads();
        int excl = run + (wid ? warpsum[wid - 1] : 0) + x - v;
        if (i < NNODES) { g_off[i] = excl; g_cur[i] = excl; }
        run += chunk_total;
        __syncthreads();
    }
    if (t == 0) g_off[NNODES] = run;
}
__global__ void k_csr(const void* __restrict__ ei) {
    int i = blockIdx.x * blockDim.x + threadIdx.x;
    if (i >= NEDGES) return;
    int s, d;
    if (g_is64) {
        s = (int)((const long long*)ei)[i];
        d = (int)((const long long*)ei)[NEDGES + i];
    } else {
        s = ((const int*)ei)[i];
        d = ((const int*)ei)[NEDGES + i];
    }
    int pos = atomicAdd(&g_cur[d], 1);
    g_src[pos] = s;
}
// fused: W1 split+transpose, W2 split+transpose, c1
__global__ void k_prepw(const float* __restrict__ W1, const float* __restrict__ W2,
                        const float* __restrict__ idv) {
    int idx = blockIdx.x * blockDim.x + threadIdx.x;
    constexpr int N1 = HID * INDIM;          // 32768
    constexpr int N2 = OUTD * HID;           // 32768
    if (idx < N1) {
        int o = idx / INDIM, i = idx % INDIM;
        float v = W1[(size_t)i * HID + o];
        __nv_bfloat16 h = __float2bfloat16_rn(v);
        g_wt1_hi[idx] = h;
        g_wt1_lo[idx] = __float2bfloat16_rn(v - __bfloat162float(h));
    } else if (idx < N1 + N2) {
        int j = idx - N1;
        int o = j / HID, i = j % HID;
        float v = W2[(size_t)i * OUTD + o];
        __nv_bfloat16 h = __float2bfloat16_rn(v);
        g_wt2_hi[j] = h;
        g_wt2_lo[j] = __float2bfloat16_rn(v - __bfloat162float(h));
    } else if (idx < N1 + N2 + HID) {
        int j = idx - N1 - N2;
        float s = 0.f;
#pragma unroll
        for (int t = 0; t < ADDDIM; t++) s += idv[t] * W1[(size_t)(INDIM + t) * HID + j];
        g_c1[j] = s;
    }
}

// -------------------- gather1: agg(x) -> bf16 hi/lo + q ---------------------
__global__ __launch_bounds__(256) void k_gather1(const float* __restrict__ x) {
    const int lane = threadIdx.x & 31;
    const int node = (blockIdx.x * blockDim.x + threadIdx.x) >> 5;
    if (node >= NNODES) return;
    const float dv = g_dinv[node];
    const int e0 = g_off[node], e1 = g_off[node + 1];
    float4 acc = make_float4(0.f, 0.f, 0.f, 0.f);
    float q = 0.f;
    int e = e0;
    for (; e + 2 <= e1; e += 2) {
        int s0 = __ldg(&g_src[e]), s1 = __ldg(&g_src[e + 1]);
        float w0 = __ldg(&g_dinv[s0]) * dv;
        float w1 = __ldg(&g_dinv[s1]) * dv;
        q += w0 + w1;
        float4 v0 = __ldg((const float4*)(x + (size_t)s0 * INDIM) + lane);
        float4 v1 = __ldg((const float4*)(x + (size_t)s1 * INDIM) + lane);
        acc.x += v0.x * w0 + v1.x * w1;
        acc.y += v0.y * w0 + v1.y * w1;
        acc.z += v0.z * w0 + v1.z * w1;
        acc.w += v0.w * w0 + v1.w * w1;
    }
    if (e < e1) {
        int s0 = __ldg(&g_src[e]);
        float w0 = __ldg(&g_dinv[s0]) * dv;
        q += w0;
        float4 v0 = __ldg((const float4*)(x + (size_t)s0 * INDIM) + lane);
        acc.x += v0.x * w0; acc.y += v0.y * w0;
        acc.z += v0.z * w0; acc.w += v0.w * w0;
    }
    {
        float w = dv * dv;
        q += w;
        float4 v = __ldg((const float4*)(x + (size_t)node * INDIM) + lane);
        acc.x += v.x * w; acc.y += v.y * w; acc.z += v.z * w; acc.w += v.w * w;
    }
    float vals[4] = {acc.x, acc.y, acc.z, acc.w};
    uint32_t hp[2], lp[2];
#pragma unroll
    for (int p = 0; p < 2; p++) {
        __nv_bfloat16 h0 = __float2bfloat16_rn(vals[p * 2]);
        __nv_bfloat16 h1 = __float2bfloat16_rn(vals[p * 2 + 1]);
        __nv_bfloat16 l0 = __float2bfloat16_rn(vals[p * 2] - __bfloat162float(h0));
        __nv_bfloat16 l1 = __float2bfloat16_rn(vals[p * 2 + 1] - __bfloat162float(h1));
        hp[p] = (uint32_t)__bfloat16_as_ushort(h0) | ((uint32_t)__bfloat16_as_ushort(h1) << 16);
        lp[p] = (uint32_t)__bfloat16_as_ushort(l0) | ((uint32_t)__bfloat16_as_ushort(l1) << 16);
    }
    size_t base = (size_t)node * INDIM + lane * 4;
    *(uint2*)&g_aggx_hi[base] = make_uint2(hp[0], hp[1]);
    *(uint2*)&g_aggx_lo[base] = make_uint2(lp[0], lp[1]);
    if (lane == 0) g_q[node] = q;
}

// -------------------- double-buffered split-bf16 GEMM -----------------------
// C[M,NTOT] = (Ahi+Alo) @ (Bhi+Blo)^T, 3-term. CTA 128x128, 8 warps, BK=32.
// smem: 2 buffers x 4 tiles (Ahi,Alo,Bhi,Blo), each 128 x SA(=40) bf16.
template <int K, int NTOT, bool L1>
__global__ __launch_bounds__(256) void k_mma(
    const __nv_bfloat16* __restrict__ Ahi, const __nv_bfloat16* __restrict__ Alo,
    const __nv_bfloat16* __restrict__ Bhi, const __nv_bfloat16* __restrict__ Blo,
    const float* __restrict__ bias, const float* __restrict__ slope,
    __nv_bfloat16* __restrict__ OutHi, __nv_bfloat16* __restrict__ OutLo,
    float* __restrict__ OutF, int M) {
    constexpr int BK = 32, SA = 40;
    constexpr int NSEG = K / BK;
    constexpr int TILE = 128 * SA;           // bf16 elems per tile

    extern __shared__ __align__(16) __nv_bfloat16 smem[];

    const int t = threadIdx.x;
    const int lane = t & 31, warp = t >> 5;
    const int wm0 = (warp >> 1) * 32;
    const int wn0 = (warp & 1) * 64;
    const int row0 = blockIdx.y * 128;
    const int n0 = blockIdx.x * 128;

    // cp.async mapping: 4 tiles x 128 rows x 2 chunks(16B) = 1024 chunks; 256 thr x 4
    // thread handles (tile-independent): row lr, chunk lc of each tile
    const int lr = t >> 1;                    // 0..127
    const int lc = t & 1;                     // chunk pair base: handles lc and lc+2

    const __nv_bfloat16* gsrc[4] = {Ahi, Alo, Bhi, Blo};

    auto load_seg = [&](int seg, int b) {
        const int k0 = seg * BK;
        const uint32_t sbase = smem_u32(smem) + (uint32_t)b * 4 * TILE * 2;
#pragma unroll
        for (int tl = 0; tl < 4; tl++) {
            const bool isA = (tl < 2);
            int grow = (isA ? row0 : n0) + lr;
            const __nv_bfloat16* gp = gsrc[tl] + (size_t)grow * K + k0;
            uint32_t dst = sbase + (uint32_t)(tl * TILE + lr * SA) * 2;
            uint32_t ok = (!isA || grow < M) ? 16u : 0u;
#pragma unroll
            for (int c = 0; c < 2; c++) {
                int ch = lc + c * 2;          // 0..3
                cp16(dst + ch * 16, gp + ch * 8, ok);
            }
        }
        cp_commit();
    };

    float acc[2][8][4] = {};

    load_seg(0, 0);
    for (int s = 0; s < NSEG; s++) {
        const int b = s & 1;
        if (s + 1 < NSEG) load_seg(s + 1, b ^ 1);
        if (s + 1 < NSEG) cp_wait<1>(); else cp_wait<0>();
        __syncthreads();

        const uint32_t sb = smem_u32(smem) + (uint32_t)b * 4 * TILE * 2;
        const uint32_t aHi = sb, aLo = sb + TILE * 2;
        const uint32_t bHi = sb + 2 * TILE * 2, bLo = sb + 3 * TILE * 2;

        // 3 phases: (aHi,bHi), (aLo,bHi), (aHi,bLo)
#pragma unroll
        for (int ph = 0; ph < 3; ph++) {
            const uint32_t at = (ph == 1) ? aLo : aHi;
            const uint32_t bt = (ph == 2) ? bLo : bHi;
#pragma unroll
            for (int kh = 0; kh < 2; kh++) {  // two k16 halves of BK=32
                uint32_t af[2][4], bf[4][4];
#pragma unroll
                for (int mi = 0; mi < 2; mi++) {
                    uint32_t addr = at +
                        ((wm0 + mi * 16 + (lane & 15)) * SA + kh * 16 + (lane >> 4) * 8) * 2;
                    ldsm_x4(af[mi], addr);
                }
#pragma unroll
                for (int nq = 0; nq < 4; nq++) {
                    uint32_t addr = bt +
                        ((wn0 + nq * 16 + (lane & 7) + ((lane >> 4) & 1) * 8) * SA +
                         kh * 16 + ((lane >> 3) & 1) * 8) * 2;
                    ldsm_x4(bf[nq], addr);
                }
#pragma unroll
                for (int mi = 0; mi < 2; mi++)
#pragma unroll
                    for (int nq = 0; nq < 4; nq++) {
                        mma_bf16(acc[mi][nq * 2],     af[mi], bf[nq][0], bf[nq][1]);
                        mma_bf16(acc[mi][nq * 2 + 1], af[mi], bf[nq][2], bf[nq][3]);
                    }
            }
        }
        __syncthreads();
    }

    // -------------------- epilogue ------------------------------------------
    float qv[2][2];
    if (L1) {
#pragma unroll
        for (int mi = 0; mi < 2; mi++) {
            int r0 = row0 + wm0 + mi * 16 + (lane >> 2);
            qv[mi][0] = (r0 < M) ? __ldg(&g_q[r0]) : 0.f;
            qv[mi][1] = (r0 + 8 < M) ? __ldg(&g_q[r0 + 8]) : 0.f;
        }
    }
#pragma unroll
    for (int mi = 0; mi < 2; mi++) {
        int r0 = row0 + wm0 + mi * 16 + (lane >> 2);
#pragma unroll
        for (int nt = 0; nt < 8; nt++) {
            int c0 = n0 + wn0 + nt * 8 + (lane & 3) * 2;
            if (L1) {
                float cc0 = __ldg(&g_c1[c0]),   cc1 = __ldg(&g_c1[c0 + 1]);
                float bb0 = __ldg(&bias[c0]),   bb1 = __ldg(&bias[c0 + 1]);
                float ss0 = __ldg(&slope[c0]),  ss1 = __ldg(&slope[c0 + 1]);
#pragma unroll
                for (int h = 0; h < 2; h++) {
                    int r = r0 + h * 8;
                    if (r >= M) continue;
                    float v0 = acc[mi][nt][h * 2]     + qv[mi][h] * cc0 + bb0;
                    float v1 = acc[mi][nt][h * 2 + 1] + qv[mi][h] * cc1 + bb1;
                    v0 = v0 >= 0.f ? v0 : ss0 * v0;
                    v1 = v1 >= 0.f ? v1 : ss1 * v1;
                    __nv_bfloat16 h0 = __float2bfloat16_rn(v0);
                    __nv_bfloat16 h1 = __float2bfloat16_rn(v1);
                    __nv_bfloat16 l0 = __float2bfloat16_rn(v0 - __bfloat162float(h0));
                    __nv_bfloat16 l1 = __float2bfloat16_rn(v1 - __bfloat162float(h1));
                    size_t o = (size_t)r * NTOT + c0;
                    *(uint32_t*)(OutHi + o) = (uint32_t)__bfloat16_as_ushort(h0) |
                                              ((uint32_t)__bfloat16_as_ushort(h1) << 16);
                    *(uint32_t*)(OutLo + o) = (uint32_t)__bfloat16_as_ushort(l0) |
                                              ((uint32_t)__bfloat16_as_ushort(l1) << 16);
                }
            } else {
#pragma unroll
                for (int h = 0; h < 2; h++) {
                    int r = r0 + h * 8;
                    if (r >= M) continue;
                    *(float2*)(OutF + (size_t)r * NTOT + c0) =
                        make_float2(acc[mi][nt][h * 2], acc[mi][nt][h * 2 + 1]);
                }
            }
        }
    }
}

// -------------------- gather2: 128-dim, fused bias+prelu --------------------
__global__ __launch_bounds__(256) void k_gather2(const float* __restrict__ bias,
                                                 const float* __restrict__ slope,
                                                 float* __restrict__ out) {
    const int lane = threadIdx.x & 31;
    const int node = (blockIdx.x * blockDim.x + threadIdx.x) >> 5;
    if (node >= NNODES) return;
    const float dv = g_dinv[node];
    const int e0 = g_off[node], e1 = g_off[node + 1];
    float4 acc = make_float4(0.f, 0.f, 0.f, 0.f);
    const float* h = g_h2;
    int e = e0;
    for (; e + 2 <= e1; e += 2) {
        int s0 = __ldg(&g_src[e]), s1 = __ldg(&g_src[e + 1]);
        float w0 = __ldg(&g_dinv[s0]) * dv;
        float w1 = __ldg(&g_dinv[s1]) * dv;
        float4 v0 = __ldg((const float4*)(h + (size_t)s0 * OUTD) + lane);
        float4 v1 = __ldg((const float4*)(h + (size_t)s1 * OUTD) + lane);
        acc.x += v0.x * w0 + v1.x * w1;
        acc.y += v0.y * w0 + v1.y * w1;
        acc.z += v0.z * w0 + v1.z * w1;
        acc.w += v0.w * w0 + v1.w * w1;
    }
    if (e < e1) {
        int s0 = __ldg(&g_src[e]);
        float w0 = __ldg(&g_dinv[s0]) * dv;
        float4 v0 = __ldg((const float4*)(h + (size_t)s0 * OUTD) + lane);
        acc.x += v0.x * w0; acc.y += v0.y * w0;
        acc.z += v0.z * w0; acc.w += v0.w * w0;
    }
    {
        float w = dv * dv;
        float4 v = __ldg((const float4*)(h + (size_t)node * OUTD) + lane);
        acc.x += v.x * w; acc.y += v.y * w; acc.z += v.z * w; acc.w += v.w * w;
    }
    float4 B = *(const float4*)&bias[lane * 4];
    float4 S = *(const float4*)&slope[lane * 4];
    float r0 = acc.x + B.x, r1 = acc.y + B.y, r2 = acc.z + B.z, r3 = acc.w + B.w;
    float4 o;
    o.x = r0 >= 0.f ? r0 : S.x * r0;
    o.y = r1 >= 0.f ? r1 : S.y * r1;
    o.z = r2 >= 0.f ? r2 : S.z * r2;
    o.w = r3 >= 0.f ? r3 : S.w * r3;
    *(float4*)&out[(size_t)node * OUTD + lane * 4] = o;
}

// -------------------- launch ------------------------------------------------
extern "C" void kernel_launch(void* const* d_in, const int* in_sizes, int n_in,
                              void* d_out, int out_size) {
    const float* x  = (const float*)d_in[0];
    const void*  ei = d_in[1];
    const float* idv = (const float*)d_in[2];
    const float* W1 = (const float*)d_in[3];
    const float* b1 = (const float*)d_in[4];
    const float* a1 = (const float*)d_in[5];
    const float* W2 = (const float*)d_in[6];
    const float* b2 = (const float*)d_in[7];
    const float* a2 = (const float*)d_in[8];
    float* out = (float*)d_out;

    __nv_bfloat16 *d_axh, *d_axl, *d_h1h, *d_h1l, *d_w1h, *d_w1l, *d_w2h, *d_w2l;
    float *d_h2;
    cudaGetSymbolAddress((void**)&d_axh, g_aggx_hi);
    cudaGetSymbolAddress((void**)&d_axl, g_aggx_lo);
    cudaGetSymbolAddress((void**)&d_h1h, g_h1_hi);
    cudaGetSymbolAddress((void**)&d_h1l, g_h1_lo);
    cudaGetSymbolAddress((void**)&d_w1h, g_wt1_hi);
    cudaGetSymbolAddress((void**)&d_w1l, g_wt1_lo);
    cudaGetSymbolAddress((void**)&d_w2h, g_wt2_hi);
    cudaGetSymbolAddress((void**)&d_w2l, g_wt2_lo);
    cudaGetSymbolAddress((void**)&d_h2, g_h2);

    const int T = 256;
    constexpr int SMEM_MMA = 2 * 4 * 128 * 40 * 2;   // 81920 B

    static bool attr_done = false;
    if (!attr_done) {
        cudaFuncSetAttribute(k_mma<INDIM, HID, true>,
                             cudaFuncAttributeMaxDynamicSharedMemorySize, SMEM_MMA);
        cudaFuncSetAttribute(k_mma<HID, OUTD, false>,
                             cudaFuncAttributeMaxDynamicSharedMemorySize, SMEM_MMA);
        attr_done = true;
    }

    k_detect_zero<<<(NNODES + T - 1) / T, T>>>((const long long*)ei);
    k_deg<<<(NEDGES + T - 1) / T, T>>>(ei);
    k_scan<<<1, 1024>>>();
    k_csr<<<(NEDGES + T - 1) / T, T>>>(ei);
    k_prepw<<<(HID * INDIM + OUTD * HID + HID + T - 1) / T, T>>>(W1, W2, idv);

    k_gather1<<<(NNODES * 32 + T - 1) / T, T>>>(x);

    {   // GEMM1: [50000,128] x [256,128]^T -> h1 bf16 hi/lo (fused epilogue)
        dim3 grid(HID / 128, (NNODES + 127) / 128);
        k_mma<INDIM, HID, true><<<grid, 256, SMEM_MMA>>>(
            d_axh, d_axl, d_w1h, d_w1l, b1, a1, d_h1h, d_h1l, nullptr, NNODES);
    }
    {   // GEMM2: [50000,256] x [128,256]^T -> h2 fp32
        dim3 grid(OUTD / 128, (NNODES + 127) / 128);
        k_mma<HID, OUTD, false><<<grid, 256, SMEM_MMA>>>(
            d_h1h, d_h1l, d_w2h, d_w2l, nullptr, nullptr, nullptr, nullptr,
            d_h2, NNODES);
    }
    k_gather2<<<(NNODES * 32 + T - 1) / T, T>>>(b2, a2, out);
}

// round 6
// speedup vs baseline: 4.0928x; 1.0039x over previous
#include <cuda_runtime.h>
#include <cuda_bf16.h>
#include <cstdint>

// ---------------------------------------------------------------------------
// 2-layer GCN. CSR gather + split-bf16 mma.sync GEMMs (double-buffered cp.async)
// ---------------------------------------------------------------------------

static constexpr int NNODES = 50000;
static constexpr int NEDGES = 800000;
static constexpr int INDIM  = 128;
static constexpr int ADDDIM = 8;
static constexpr int HID    = 256;
static constexpr int OUTD   = 128;

// -------------------- device scratch ----------------------------------------
__device__ __align__(16) __nv_bfloat16 g_aggx_hi[(size_t)NNODES * INDIM];
__device__ __align__(16) __nv_bfloat16 g_aggx_lo[(size_t)NNODES * INDIM];
__device__ __align__(16) __nv_bfloat16 g_h1_hi[(size_t)NNODES * HID];
__device__ __align__(16) __nv_bfloat16 g_h1_lo[(size_t)NNODES * HID];
__device__ __align__(16) float g_h2[(size_t)NNODES * OUTD];
__device__ float g_q[NNODES];
__device__ float g_dinv[NNODES];
__device__ int   g_deg[NNODES];
__device__ int   g_off[NNODES + 1];
__device__ int   g_cur[NNODES];
__device__ int   g_src[NEDGES];
__device__ float g_c1[HID];
__device__ __align__(16) __nv_bfloat16 g_wt1_hi[HID * INDIM], g_wt1_lo[HID * INDIM];
__device__ __align__(16) __nv_bfloat16 g_wt2_hi[OUTD * HID],  g_wt2_lo[OUTD * HID];
__device__ int g_is64;

// -------------------- asm helpers -------------------------------------------
__device__ __forceinline__ uint32_t smem_u32(const void* p) {
    return (uint32_t)__cvta_generic_to_shared(p);
}
__device__ __forceinline__ void ldsm_x4(uint32_t r[4], uint32_t addr) {
    asm volatile("ldmatrix.sync.aligned.m8n8.x4.shared.b16 {%0,%1,%2,%3}, [%4];"
                 : "=r"(r[0]), "=r"(r[1]), "=r"(r[2]), "=r"(r[3]) : "r"(addr));
}
__device__ __forceinline__ void mma_bf16(float* c, const uint32_t* a,
                                         uint32_t b0, uint32_t b1) {
    asm volatile(
        "mma.sync.aligned.m16n8k16.row.col.f32.bf16.bf16.f32 "
        "{%0,%1,%2,%3}, {%4,%5,%6,%7}, {%8,%9}, {%0,%1,%2,%3};"
        : "+f"(c[0]), "+f"(c[1]), "+f"(c[2]), "+f"(c[3])
        : "r"(a[0]), "r"(a[1]), "r"(a[2]), "r"(a[3]), "r"(b0), "r"(b1));
}
__device__ __forceinline__ void cp16(uint32_t dst, const void* src, uint32_t sz) {
    asm volatile("cp.async.cg.shared.global [%0], [%1], 16, %2;"
                 :: "r"(dst), "l"(src), "r"(sz) : "memory");
}
__device__ __forceinline__ void cp_commit() {
    asm volatile("cp.async.commit_group;" ::: "memory");
}
template <int N>
__device__ __forceinline__ void cp_wait() {
    asm volatile("cp.async.wait_group %0;" :: "n"(N) : "memory");
}

// -------------------- prep kernels ------------------------------------------
__global__ void k_detect_zero(const long long* __restrict__ ei) {
    int i = blockIdx.x * blockDim.x + threadIdx.x;
    if (i < NNODES) g_deg[i] = 0;
    if (blockIdx.x == 0 && threadIdx.x < 32) {
        bool bad = false;
        for (int j = threadIdx.x; j < 512; j += 32) {
            long long v = ei[j];
            if (v < 0 || v >= NNODES) bad = true;
        }
        unsigned m = __ballot_sync(0xFFFFFFFFu, bad);
        if (threadIdx.x == 0) g_is64 = (m == 0u) ? 1 : 0;
    }
}
// 2 edges per thread
__global__ void k_deg(const void* __restrict__ ei) {
    int i = blockIdx.x * blockDim.x + threadIdx.x;       // pair index
    if (i >= NEDGES / 2) return;
    int d0, d1;
    if (g_is64) {
        longlong2 v = __ldg((const longlong2*)ei + NEDGES / 2 + i);
        d0 = (int)v.x; d1 = (int)v.y;
    } else {
        int2 v = __ldg((const int2*)ei + NEDGES / 2 + i);
        d0 = v.x; d1 = v.y;
    }
    atomicAdd(&g_deg[d0], 1);
    atomicAdd(&g_deg[d1], 1);
}
// scan over 2 elems/thread; also writes dinv
__global__ void k_scan() {
    __shared__ int warpsum[32];
    __shared__ int chunk_total;
    const int t = threadIdx.x;               // 1024
    const int lane = t & 31, wid = t >> 5;
    int run = 0;
    for (int base = 0; base < NNODES; base += 2048) {
        int i0 = base + t * 2, i1 = i0 + 1;
        int v0 = (i0 < NNODES) ? g_deg[i0] : 0;
        int v1 = (i1 < NNODES) ? g_deg[i1] : 0;
        if (i0 < NNODES) g_dinv[i0] = rsqrtf((float)(v0 + 1));
        if (i1 < NNODES) g_dinv[i1] = rsqrtf((float)(v1 + 1));
        int v = v0 + v1;
        int x = v;
#pragma unroll
        for (int o = 1; o < 32; o <<= 1) {
            int y = __shfl_up_sync(0xFFFFFFFFu, x, o);
            if (lane >= o) x += y;
        }
        if (lane == 31) warpsum[wid] = x;
        __syncthreads();
        if (wid == 0) {
            int w = warpsum[lane];
#pragma unroll
            for (int o = 1; o < 32; o <<= 1) {
                int y = __shfl_up_sync(0xFFFFFFFFu, w, o);
                if (lane >= o) w += y;
            }
            warpsum[lane] = w;
            if (lane == 31) chunk_total = w;
        }
        __syncthreads();
        int excl = run + (wid ? warpsum[wid - 1] : 0) + x - v;
        if (i0 < NNODES) { g_off[i0] = excl; g_cur[i0] = excl; }
        if (i1 < NNODES) { g_off[i1] = excl + v0; g_cur[i1] = excl + v0; }
        run += chunk_total;
        __syncthreads();
    }
    if (t == 0) g_off[NNODES] = run;
}
// 2 edges per thread
__global__ void k_csr(const void* __restrict__ ei) {
    int i = blockIdx.x * blockDim.x + threadIdx.x;       // pair index
    if (i >= NEDGES / 2) return;
    int s0, s1, d0, d1;
    if (g_is64) {
        longlong2 sv = __ldg((const longlong2*)ei + i);
        longlong2 dv = __ldg((const longlong2*)ei + NEDGES / 2 + i);
        s0 = (int)sv.x; s1 = (int)sv.y; d0 = (int)dv.x; d1 = (int)dv.y;
    } else {
        int2 sv = __ldg((const int2*)ei + i);
        int2 dv = __ldg((const int2*)ei + NEDGES / 2 + i);
        s0 = sv.x; s1 = sv.y; d0 = dv.x; d1 = dv.y;
    }
    int p0 = atomicAdd(&g_cur[d0], 1);
    g_src[p0] = s0;
    int p1 = atomicAdd(&g_cur[d1], 1);
    g_src[p1] = s1;
}
// fused: W1 split+transpose, W2 split+transpose, c1
__global__ void k_prepw(const float* __restrict__ W1, const float* __restrict__ W2,
                        const float* __restrict__ idv) {
    int idx = blockIdx.x * blockDim.x + threadIdx.x;
    constexpr int N1 = HID * INDIM;
    constexpr int N2 = OUTD * HID;
    if (idx < N1) {
        int o = idx / INDIM, i = idx % INDIM;
        float v = W1[(size_t)i * HID + o];
        __nv_bfloat16 h = __float2bfloat16_rn(v);
        g_wt1_hi[idx] = h;
        g_wt1_lo[idx] = __float2bfloat16_rn(v - __bfloat162float(h));
    } else if (idx < N1 + N2) {
        int j = idx - N1;
        int o = j / HID, i = j % HID;
        float v = W2[(size_t)i * OUTD + o];
        __nv_bfloat16 h = __float2bfloat16_rn(v);
        g_wt2_hi[j] = h;
        g_wt2_lo[j] = __float2bfloat16_rn(v - __bfloat162float(h));
    } else if (idx < N1 + N2 + HID) {
        int j = idx - N1 - N2;
        float s = 0.f;
#pragma unroll
        for (int t = 0; t < ADDDIM; t++) s += idv[t] * W1[(size_t)(INDIM + t) * HID + j];
        g_c1[j] = s;
    }
}

// -------------------- gather1: agg(x) -> bf16 hi/lo + q ---------------------
__global__ __launch_bounds__(256) void k_gather1(const float* __restrict__ x) {
    const int lane = threadIdx.x & 31;
    const int node = (blockIdx.x * blockDim.x + threadIdx.x) >> 5;
    if (node >= NNODES) return;
    const float dv = g_dinv[node];
    const int e0 = g_off[node], e1 = g_off[node + 1];
    float4 acc = make_float4(0.f, 0.f, 0.f, 0.f);
    float q = 0.f;
    int e = e0;
    for (; e + 4 <= e1; e += 4) {
        int s0 = __ldg(&g_src[e]),     s1 = __ldg(&g_src[e + 1]);
        int s2 = __ldg(&g_src[e + 2]), s3 = __ldg(&g_src[e + 3]);
        float w0 = __ldg(&g_dinv[s0]) * dv, w1 = __ldg(&g_dinv[s1]) * dv;
        float w2 = __ldg(&g_dinv[s2]) * dv, w3 = __ldg(&g_dinv[s3]) * dv;
        q += (w0 + w1) + (w2 + w3);
        float4 v0 = __ldg((const float4*)(x + (size_t)s0 * INDIM) + lane);
        float4 v1 = __ldg((const float4*)(x + (size_t)s1 * INDIM) + lane);
        float4 v2 = __ldg((const float4*)(x + (size_t)s2 * INDIM) + lane);
        float4 v3 = __ldg((const float4*)(x + (size_t)s3 * INDIM) + lane);
        acc.x += v0.x * w0 + v1.x * w1 + v2.x * w2 + v3.x * w3;
        acc.y += v0.y * w0 + v1.y * w1 + v2.y * w2 + v3.y * w3;
        acc.z += v0.z * w0 + v1.z * w1 + v2.z * w2 + v3.z * w3;
        acc.w += v0.w * w0 + v1.w * w1 + v2.w * w2 + v3.w * w3;
    }
    for (; e < e1; e++) {
        int s0 = __ldg(&g_src[e]);
        float w0 = __ldg(&g_dinv[s0]) * dv;
        q += w0;
        float4 v0 = __ldg((const float4*)(x + (size_t)s0 * INDIM) + lane);
        acc.x += v0.x * w0; acc.y += v0.y * w0;
        acc.z += v0.z * w0; acc.w += v0.w * w0;
    }
    {
        float w = dv * dv;
        q += w;
        float4 v = __ldg((const float4*)(x + (size_t)node * INDIM) + lane);
        acc.x += v.x * w; acc.y += v.y * w; acc.z += v.z * w; acc.w += v.w * w;
    }
    float vals[4] = {acc.x, acc.y, acc.z, acc.w};
    uint32_t hp[2], lp[2];
#pragma unroll
    for (int p = 0; p < 2; p++) {
        __nv_bfloat16 h0 = __float2bfloat16_rn(vals[p * 2]);
        __nv_bfloat16 h1 = __float2bfloat16_rn(vals[p * 2 + 1]);
        __nv_bfloat16 l0 = __float2bfloat16_rn(vals[p * 2] - __bfloat162float(h0));
        __nv_bfloat16 l1 = __float2bfloat16_rn(vals[p * 2 + 1] - __bfloat162float(h1));
        hp[p] = (uint32_t)__bfloat16_as_ushort(h0) | ((uint32_t)__bfloat16_as_ushort(h1) << 16);
        lp[p] = (uint32_t)__bfloat16_as_ushort(l0) | ((uint32_t)__bfloat16_as_ushort(l1) << 16);
    }
    size_t base = (size_t)node * INDIM + lane * 4;
    *(uint2*)&g_aggx_hi[base] = make_uint2(hp[0], hp[1]);
    *(uint2*)&g_aggx_lo[base] = make_uint2(lp[0], lp[1]);
    if (lane == 0) g_q[node] = q;
}

// -------------------- double-buffered split-bf16 GEMM -----------------------
template <int K, int NTOT, bool L1>
__global__ __launch_bounds__(256) void k_mma(
    const __nv_bfloat16* __restrict__ Ahi, const __nv_bfloat16* __restrict__ Alo,
    const __nv_bfloat16* __restrict__ Bhi, const __nv_bfloat16* __restrict__ Blo,
    const float* __restrict__ bias, const float* __restrict__ slope,
    __nv_bfloat16* __restrict__ OutHi, __nv_bfloat16* __restrict__ OutLo,
    float* __restrict__ OutF, int M) {
    constexpr int BK = 32, SA = 40;
    constexpr int NSEG = K / BK;
    constexpr int TILE = 128 * SA;

    extern __shared__ __align__(16) __nv_bfloat16 smem[];

    const int t = threadIdx.x;
    const int lane = t & 31, warp = t >> 5;
    const int wm0 = (warp >> 1) * 32;
    const int wn0 = (warp & 1) * 64;
    const int row0 = blockIdx.y * 128;
    const int n0 = blockIdx.x * 128;

    const int lr = t >> 1;
    const int lc = t & 1;

    const __nv_bfloat16* gsrc[4] = {Ahi, Alo, Bhi, Blo};

    auto load_seg = [&](int seg, int b) {
        const int k0 = seg * BK;
        const uint32_t sbase = smem_u32(smem) + (uint32_t)b * 4 * TILE * 2;
#pragma unroll
        for (int tl = 0; tl < 4; tl++) {
            const bool isA = (tl < 2);
            int grow = (isA ? row0 : n0) + lr;
            const __nv_bfloat16* gp = gsrc[tl] + (size_t)grow * K + k0;
            uint32_t dst = sbase + (uint32_t)(tl * TILE + lr * SA) * 2;
            uint32_t ok = (!isA || grow < M) ? 16u : 0u;
#pragma unroll
            for (int c = 0; c < 2; c++) {
                int ch = lc + c * 2;
                cp16(dst + ch * 16, gp + ch * 8, ok);
            }
        }
        cp_commit();
    };

    float acc[2][8][4] = {};

    load_seg(0, 0);
    for (int s = 0; s < NSEG; s++) {
        const int b = s & 1;
        if (s + 1 < NSEG) load_seg(s + 1, b ^ 1);
        if (s + 1 < NSEG) cp_wait<1>(); else cp_wait<0>();
        __syncthreads();

        const uint32_t sb = smem_u32(smem) + (uint32_t)b * 4 * TILE * 2;
        const uint32_t aHi = sb, aLo = sb + TILE * 2;
        const uint32_t bHi = sb + 2 * TILE * 2, bLo = sb + 3 * TILE * 2;

#pragma unroll
        for (int ph = 0; ph < 3; ph++) {
            const uint32_t at = (ph == 1) ? aLo : aHi;
            const uint32_t bt = (ph == 2) ? bLo : bHi;
#pragma unroll
            for (int kh = 0; kh < 2; kh++) {
                uint32_t af[2][4], bf[4][4];
#pragma unroll
                for (int mi = 0; mi < 2; mi++) {
                    uint32_t addr = at +
                        ((wm0 + mi * 16 + (lane & 15)) * SA + kh * 16 + (lane >> 4) * 8) * 2;
                    ldsm_x4(af[mi], addr);
                }
#pragma unroll
                for (int nq = 0; nq < 4; nq++) {
                    uint32_t addr = bt +
                        ((wn0 + nq * 16 + (lane & 7) + ((lane >> 4) & 1) * 8) * SA +
                         kh * 16 + ((lane >> 3) & 1) * 8) * 2;
                    ldsm_x4(bf[nq], addr);
                }
#pragma unroll
                for (int mi = 0; mi < 2; mi++)
#pragma unroll
                    for (int nq = 0; nq < 4; nq++) {
                        mma_bf16(acc[mi][nq * 2],     af[mi], bf[nq][0], bf[nq][1]);
                        mma_bf16(acc[mi][nq * 2 + 1], af[mi], bf[nq][2], bf[nq][3]);
                    }
            }
        }
        __syncthreads();
    }

    // epilogue
    float qv[2][2];
    if (L1) {
#pragma unroll
        for (int mi = 0; mi < 2; mi++) {
            int r0 = row0 + wm0 + mi * 16 + (lane >> 2);
            qv[mi][0] = (r0 < M) ? __ldg(&g_q[r0]) : 0.f;
            qv[mi][1] = (r0 + 8 < M) ? __ldg(&g_q[r0 + 8]) : 0.f;
        }
    }
#pragma unroll
    for (int mi = 0; mi < 2; mi++) {
        int r0 = row0 + wm0 + mi * 16 + (lane >> 2);
#pragma unroll
        for (int nt = 0; nt < 8; nt++) {
            int c0 = n0 + wn0 + nt * 8 + (lane & 3) * 2;
            if (L1) {
                float cc0 = __ldg(&g_c1[c0]),   cc1 = __ldg(&g_c1[c0 + 1]);
                float bb0 = __ldg(&bias[c0]),   bb1 = __ldg(&bias[c0 + 1]);
                float ss0 = __ldg(&slope[c0]),  ss1 = __ldg(&slope[c0 + 1]);
#pragma unroll
                for (int h = 0; h < 2; h++) {
                    int r = r0 + h * 8;
                    if (r >= M) continue;
                    float v0 = acc[mi][nt][h * 2]     + qv[mi][h] * cc0 + bb0;
                    float v1 = acc[mi][nt][h * 2 + 1] + qv[mi][h] * cc1 + bb1;
                    v0 = v0 >= 0.f ? v0 : ss0 * v0;
                    v1 = v1 >= 0.f ? v1 : ss1 * v1;
                    __nv_bfloat16 h0 = __float2bfloat16_rn(v0);
                    __nv_bfloat16 h1 = __float2bfloat16_rn(v1);
                    __nv_bfloat16 l0 = __float2bfloat16_rn(v0 - __bfloat162float(h0));
                    __nv_bfloat16 l1 = __float2bfloat16_rn(v1 - __bfloat162float(h1));
                    size_t o = (size_t)r * NTOT + c0;
                    *(uint32_t*)(OutHi + o) = (uint32_t)__bfloat16_as_ushort(h0) |
                                              ((uint32_t)__bfloat16_as_ushort(h1) << 16);
                    *(uint32_t*)(OutLo + o) = (uint32_t)__bfloat16_as_ushort(l0) |
                                              ((uint32_t)__bfloat16_as_ushort(l1) << 16);
                }
            } else {
#pragma unroll
                for (int h = 0; h < 2; h++) {
                    int r = r0 + h * 8;
                    if (r >= M) continue;
                    *(float2*)(OutF + (size_t)r * NTOT + c0) =
                        make_float2(acc[mi][nt][h * 2], acc[mi][nt][h * 2 + 1]);
                }
            }
        }
    }
}

// -------------------- gather2: 128-dim, fused bias+prelu --------------------
__global__ __launch_bounds__(256) void k_gather2(const float* __restrict__ bias,
                                                 const float* __restrict__ slope,
                                                 float* __restrict__ out) {
    const int lane = threadIdx.x & 31;
    const int node = (blockIdx.x * blockDim.x + threadIdx.x) >> 5;
    if (node >= NNODES) return;
    const float dv = g_dinv[node];
    const int e0 = g_off[node], e1 = g_off[node + 1];
    float4 acc = make_float4(0.f, 0.f, 0.f, 0.f);
    const float* h = g_h2;
    int e = e0;
    for (; e + 4 <= e1; e += 4) {
        int s0 = __ldg(&g_src[e]),     s1 = __ldg(&g_src[e + 1]);
        int s2 = __ldg(&g_src[e + 2]), s3 = __ldg(&g_src[e + 3]);
        float w0 = __ldg(&g_dinv[s0]) * dv, w1 = __ldg(&g_dinv[s1]) * dv;
        float w2 = __ldg(&g_dinv[s2]) * dv, w3 = __ldg(&g_dinv[s3]) * dv;
        float4 v0 = __ldg((const float4*)(h + (size_t)s0 * OUTD) + lane);
        float4 v1 = __ldg((const float4*)(h + (size_t)s1 * OUTD) + lane);
        float4 v2 = __ldg((const float4*)(h + (size_t)s2 * OUTD) + lane);
        float4 v3 = __ldg((const float4*)(h + (size_t)s3 * OUTD) + lane);
        acc.x += v0.x * w0 + v1.x * w1 + v2.x * w2 + v3.x * w3;
        acc.y += v0.y * w0 + v1.y * w1 + v2.y * w2 + v3.y * w3;
        acc.z += v0.z * w0 + v1.z * w1 + v2.z * w2 + v3.z * w3;
        acc.w += v0.w * w0 + v1.w * w1 + v2.w * w2 + v3.w * w3;
    }
    for (; e < e1; e++) {
        int s0 = __ldg(&g_src[e]);
        float w0 = __ldg(&g_dinv[s0]) * dv;
        float4 v0 = __ldg((const float4*)(h + (size_t)s0 * OUTD) + lane);
        acc.x += v0.x * w0; acc.y += v0.y * w0;
        acc.z += v0.z * w0; acc.w += v0.w * w0;
    }
    {
        float w = dv * dv;
        float4 v = __ldg((const float4*)(h + (size_t)node * OUTD) + lane);
        acc.x += v.x * w; acc.y += v.y * w; acc.z += v.z * w; acc.w += v.w * w;
    }
    float4 B = *(const float4*)&bias[lane * 4];
    float4 S = *(const float4*)&slope[lane * 4];
    float r0 = acc.x + B.x, r1 = acc.y + B.y, r2 = acc.z + B.z, r3 = acc.w + B.w;
    float4 o;
    o.x = r0 >= 0.f ? r0 : S.x * r0;
    o.y = r1 >= 0.f ? r1 : S.y * r1;
    o.z = r2 >= 0.f ? r2 : S.z * r2;
    o.w = r3 >= 0.f ? r3 : S.w * r3;
    *(float4*)&out[(size_t)node * OUTD + lane * 4] = o;
}

// -------------------- launch ------------------------------------------------
extern "C" void kernel_launch(void* const* d_in, const int* in_sizes, int n_in,
                              void* d_out, int out_size) {
    const float* x  = (const float*)d_in[0];
    const void*  ei = d_in[1];
    const float* idv = (const float*)d_in[2];
    const float* W1 = (const float*)d_in[3];
    const float* b1 = (const float*)d_in[4];
    const float* a1 = (const float*)d_in[5];
    const float* W2 = (const float*)d_in[6];
    const float* b2 = (const float*)d_in[7];
    const float* a2 = (const float*)d_in[8];
    float* out = (float*)d_out;

    __nv_bfloat16 *d_axh, *d_axl, *d_h1h, *d_h1l, *d_w1h, *d_w1l, *d_w2h, *d_w2l;
    float *d_h2;
    cudaGetSymbolAddress((void**)&d_axh, g_aggx_hi);
    cudaGetSymbolAddress((void**)&d_axl, g_aggx_lo);
    cudaGetSymbolAddress((void**)&d_h1h, g_h1_hi);
    cudaGetSymbolAddress((void**)&d_h1l, g_h1_lo);
    cudaGetSymbolAddress((void**)&d_w1h, g_wt1_hi);
    cudaGetSymbolAddress((void**)&d_w1l, g_wt1_lo);
    cudaGetSymbolAddress((void**)&d_w2h, g_wt2_hi);
    cudaGetSymbolAddress((void**)&d_w2l, g_wt2_lo);
    cudaGetSymbolAddress((void**)&d_h2, g_h2);

    const int T = 256;
    constexpr int SMEM_MMA = 2 * 4 * 128 * 40 * 2;   // 81920 B

    static bool attr_done = false;
    if (!attr_done) {
        cudaFuncSetAttribute(k_mma<INDIM, HID, true>,
                             cudaFuncAttributeMaxDynamicSharedMemorySize, SMEM_MMA);
        cudaFuncSetAttribute(k_mma<HID, OUTD, false>,
                             cudaFuncAttributeMaxDynamicSharedMemorySize, SMEM_MMA);
        attr_done = true;
    }

    k_detect_zero<<<(NNODES + T - 1) / T, T>>>((const long long*)ei);
    k_deg<<<(NEDGES / 2 + T - 1) / T, T>>>(ei);
    k_scan<<<1, 1024>>>();
    k_csr<<<(NEDGES / 2 + T - 1) / T, T>>>(ei);
    k_prepw<<<(HID * INDIM + OUTD * HID + HID + T - 1) / T, T>>>(W1, W2, idv);

    k_gather1<<<(NNODES * 32 + T - 1) / T, T>>>(x);

    {   // GEMM1
        dim3 grid(HID / 128, (NNODES + 127) / 128);
        k_mma<INDIM, HID, true><<<grid, 256, SMEM_MMA>>>(
            d_axh, d_axl, d_w1h, d_w1l, b1, a1, d_h1h, d_h1l, nullptr, NNODES);
    }
    {   // GEMM2
        dim3 grid(OUTD / 128, (NNODES + 127) / 128);
        k_mma<HID, OUTD, false><<<grid, 256, SMEM_MMA>>>(
            d_h1h, d_h1l, d_w2h, d_w2l, nullptr, nullptr, nullptr, nullptr,
            d_h2, NNODES);
    }
    k_gather2<<<(NNODES * 32 + T - 1) / T, T>>>(b2, a2, out);
}